// round 12
// baseline (speedup 1.0000x reference)
#include <cuda_runtime.h>
#include <math.h>
#include <mma.h>
using namespace nvcuda;

#define NMAX 50000
#define EMAX 800000
#define EPMAX (EMAX + NMAX)
#define FH 256
#define NHEADS 4
#define NBPART ((NMAX + 1023) / 1024)

// ---------------- scratch (device globals) ------------------------------------
__device__ float g_h[NMAX * FH];       // activation ping
__device__ float g_h2[NMAX * FH];      // activation pong (pre-aggregation h)
__device__ float g_as[NMAX * NHEADS];  // alpha_src per node
__device__ float g_ad[NMAX * NHEADS];  // alpha_dst per node
__device__ float g_w[EPMAX * NHEADS];  // normalized per-edge weights
__device__ int   g_off[NMAX + 1];
__device__ int   g_deg[NMAX];
__device__ int   g_cur[NMAX];
__device__ int   g_srcs[EPMAX];
__device__ int   g_part[NBPART];
__device__ int   g_ppre[NBPART];

__device__ __forceinline__ float lrelu(float x) { return x > 0.f ? x : 0.2f * x; }

// ---------------- CSR build ----------------------------------------------------
__global__ void k_zero(int n) {
    int i = blockIdx.x * blockDim.x + threadIdx.x;
    if (i < n) { g_deg[i] = 0; g_cur[i] = 0; }
}

__global__ void k_deg(const int* __restrict__ ei, int E, int n) {
    int i = blockIdx.x * blockDim.x + threadIdx.x;
    int tot = E + n;
    if (i < tot) {
        int dst = (i < E) ? ei[E + i] : (i - E);
        atomicAdd(&g_deg[dst], 1);
    }
}

__global__ __launch_bounds__(1024) void k_part(int n) {
    __shared__ int s[1024];
    int i = blockIdx.x * 1024 + threadIdx.x;
    s[threadIdx.x] = (i < n) ? g_deg[i] : 0;
    __syncthreads();
    for (int off = 512; off > 0; off >>= 1) {
        if (threadIdx.x < off) s[threadIdx.x] += s[threadIdx.x + off];
        __syncthreads();
    }
    if (threadIdx.x == 0) g_part[blockIdx.x] = s[0];
}

__global__ void k_scanp(int nb) {
    __shared__ int s[64];
    int tid = threadIdx.x;
    s[tid] = (tid < nb) ? g_part[tid] : 0;
    __syncthreads();
    for (int off = 1; off < 64; off <<= 1) {
        int t = (tid >= off) ? s[tid - off] : 0;
        __syncthreads();
        s[tid] += t;
        __syncthreads();
    }
    if (tid < nb) g_ppre[tid] = (tid == 0) ? 0 : s[tid - 1];
}

__global__ __launch_bounds__(1024) void k_offsets(int n) {
    __shared__ int s[1024];
    int b = blockIdx.x;
    int i = b * 1024 + threadIdx.x;
    int v = (i < n) ? g_deg[i] : 0;
    s[threadIdx.x] = v;
    __syncthreads();
    for (int off = 1; off < 1024; off <<= 1) {
        int t = (threadIdx.x >= off) ? s[threadIdx.x - off] : 0;
        __syncthreads();
        s[threadIdx.x] += t;
        __syncthreads();
    }
    if (i < n) g_off[i + 1] = g_ppre[b] + s[threadIdx.x];
    if (b == 0 && threadIdx.x == 0) g_off[0] = 0;
}

__global__ void k_scatter(const int* __restrict__ ei, int E, int n) {
    int i = blockIdx.x * blockDim.x + threadIdx.x;
    int tot = E + n;
    if (i < tot) {
        int src, dst;
        if (i < E) { src = ei[i]; dst = ei[E + i]; }
        else       { src = i - E; dst = src; }
        int pos = g_off[dst] + atomicAdd(&g_cur[dst], 1);
        g_srcs[pos] = src;
    }
}

// ---------------- GEMM: 128x128 block tile (layers 1-2), fused alpha -----------
// 8 warps = 4(M) x 2(N); warp tile 32x64. Requires N % 128 == 0.
__global__ __launch_bounds__(256) void k_gemm128(
    const float* __restrict__ A, const float* __restrict__ B, float* __restrict__ C,
    const float* __restrict__ aS, const float* __restrict__ aD,
    float* __restrict__ gas, float* __restrict__ gad,
    int M, int N, int K)
{
    __shared__ float smem[128 * 36 + 32 * 132];      // 8832 floats = 35328 B
    float* As = smem;                                // [128][36]
    float* Bs = smem + 128 * 36;                     // [32][132]
    float (*Cs)[68] = (float(*)[68])smem;            // epilogue alias [128][68] (8704 floats)

    int tid = threadIdx.x;
    int warp = tid >> 5;
    int wm = warp & 3, wn = warp >> 2;
    int row0 = blockIdx.y * 128, col0 = blockIdx.x * 128;
    int wr = wm * 32;
    int wc = wn * 64;

    wmma::fragment<wmma::accumulator, 16, 16, 8, float> c[2][4];
#pragma unroll
    for (int i = 0; i < 2; i++)
#pragma unroll
        for (int j = 0; j < 4; j++)
            wmma::fill_fragment(c[i][j], 0.f);

    for (int k0 = 0; k0 < K; k0 += 32) {
        // stage A 128x32
#pragma unroll
        for (int r = 0; r < 4; r++) {
            int idx = tid + r * 256;
            int m = idx >> 3;
            int kk = (idx & 7) * 4;
            float4 v = make_float4(0.f, 0.f, 0.f, 0.f);
            if (row0 + m < M) v = *(const float4*)&A[(size_t)(row0 + m) * K + k0 + kk];
            float* p = As + m * 36 + kk;
            p[0] = wmma::__float_to_tf32(v.x);
            p[1] = wmma::__float_to_tf32(v.y);
            p[2] = wmma::__float_to_tf32(v.z);
            p[3] = wmma::__float_to_tf32(v.w);
        }
        // stage B 32x128
#pragma unroll
        for (int r = 0; r < 4; r++) {
            int idx = tid + r * 256;
            int kk = idx >> 5;
            int nn = (idx & 31) * 4;
            float4 v = *(const float4*)&B[(size_t)(k0 + kk) * N + col0 + nn];
            float* p = Bs + kk * 132 + nn;
            p[0] = wmma::__float_to_tf32(v.x);
            p[1] = wmma::__float_to_tf32(v.y);
            p[2] = wmma::__float_to_tf32(v.z);
            p[3] = wmma::__float_to_tf32(v.w);
        }
        __syncthreads();
#pragma unroll
        for (int kk = 0; kk < 32; kk += 8) {
            wmma::fragment<wmma::matrix_a, 16, 16, 8, wmma::precision::tf32, wmma::row_major> a0, a1;
            wmma::fragment<wmma::matrix_b, 16, 16, 8, wmma::precision::tf32, wmma::row_major> b0, b1, b2, b3;
            wmma::load_matrix_sync(a0, As + wr * 36 + kk, 36);
            wmma::load_matrix_sync(a1, As + (wr + 16) * 36 + kk, 36);
            wmma::load_matrix_sync(b0, Bs + kk * 132 + wc, 132);
            wmma::load_matrix_sync(b1, Bs + kk * 132 + wc + 16, 132);
            wmma::load_matrix_sync(b2, Bs + kk * 132 + wc + 32, 132);
            wmma::load_matrix_sync(b3, Bs + kk * 132 + wc + 48, 132);
            wmma::mma_sync(c[0][0], a0, b0, c[0][0]);
            wmma::mma_sync(c[0][1], a0, b1, c[0][1]);
            wmma::mma_sync(c[0][2], a0, b2, c[0][2]);
            wmma::mma_sync(c[0][3], a0, b3, c[0][3]);
            wmma::mma_sync(c[1][0], a1, b0, c[1][0]);
            wmma::mma_sync(c[1][1], a1, b1, c[1][1]);
            wmma::mma_sync(c[1][2], a1, b2, c[1][2]);
            wmma::mma_sync(c[1][3], a1, b3, c[1][3]);
        }
        __syncthreads();
    }

    // epilogue in two 64-column halves; each half is exactly one head
#pragma unroll
    for (int half = 0; half < 2; half++) {
        if (wn == half) {
#pragma unroll
            for (int i = 0; i < 2; i++)
#pragma unroll
                for (int j = 0; j < 4; j++)
                    wmma::store_matrix_sync(&Cs[wr + i * 16][j * 16], c[i][j], 68, wmma::mem_row_major);
        }
        __syncthreads();

        int cbase = col0 + half * 64;
        // write C
        for (int idx = tid; idx < 128 * 64; idx += 256) {
            int m = idx >> 6, nn = idx & 63;
            if (row0 + m < M) C[(size_t)(row0 + m) * N + cbase + nn] = Cs[m][nn];
        }
        // fused alpha: 2 threads per row, 32 cols each
        {
            int r = tid >> 1;
            int hh = tid & 1;
            float ps = 0.f, pd = 0.f;
#pragma unroll
            for (int cc = 0; cc < 32; cc++) {
                float v = Cs[r][hh * 32 + cc];
                ps = fmaf(v, aS[cbase + hh * 32 + cc], ps);
                pd = fmaf(v, aD[cbase + hh * 32 + cc], pd);
            }
            ps += __shfl_down_sync(0xffffffffu, ps, 1);
            pd += __shfl_down_sync(0xffffffffu, pd, 1);
            if (hh == 0 && row0 + r < M) {
                int nh = N >> 6;
                int head = cbase >> 6;
                gas[(row0 + r) * nh + head] = ps;
                gad[(row0 + r) * nh + head] = pd;
            }
        }
        __syncthreads();
    }
}

// ---------------- GEMM: 128x64 block tile (layer 3), fused alpha ---------------
__global__ __launch_bounds__(256) void k_gemm_tc(
    const float* __restrict__ A, const float* __restrict__ B, float* __restrict__ C,
    const float* __restrict__ aS, const float* __restrict__ aD,
    float* __restrict__ gas, float* __restrict__ gad,
    int M, int N, int K)
{
    __shared__ float smem[128 * 68];
    float* As = smem;                                // [128][36]
    float* Bs = smem + 128 * 36;                     // [32][68]
    float (*Cs)[68] = (float(*)[68])smem;

    int tid = threadIdx.x;
    int warp = tid >> 5;
    int row0 = blockIdx.y * 128, col0 = blockIdx.x * 64;
    int wr = (warp & 3) * 32;
    int wc = (warp >> 2) * 32;

    wmma::fragment<wmma::accumulator, 16, 16, 8, float> c[2][2];
#pragma unroll
    for (int i = 0; i < 2; i++)
#pragma unroll
        for (int j = 0; j < 2; j++)
            wmma::fill_fragment(c[i][j], 0.f);

    for (int k0 = 0; k0 < K; k0 += 32) {
#pragma unroll
        for (int r = 0; r < 4; r++) {
            int idx = tid + r * 256;
            int m = idx >> 3;
            int kk = (idx & 7) * 4;
            float4 v = make_float4(0.f, 0.f, 0.f, 0.f);
            if (row0 + m < M) v = *(const float4*)&A[(size_t)(row0 + m) * K + k0 + kk];
            float* p = As + m * 36 + kk;
            p[0] = wmma::__float_to_tf32(v.x);
            p[1] = wmma::__float_to_tf32(v.y);
            p[2] = wmma::__float_to_tf32(v.z);
            p[3] = wmma::__float_to_tf32(v.w);
        }
#pragma unroll
        for (int r = 0; r < 2; r++) {
            int idx = tid + r * 256;
            int kk = idx >> 4;
            int nn = (idx & 15) * 4;
            float4 v = *(const float4*)&B[(size_t)(k0 + kk) * N + col0 + nn];
            float* p = Bs + kk * 68 + nn;
            p[0] = wmma::__float_to_tf32(v.x);
            p[1] = wmma::__float_to_tf32(v.y);
            p[2] = wmma::__float_to_tf32(v.z);
            p[3] = wmma::__float_to_tf32(v.w);
        }
        __syncthreads();
#pragma unroll
        for (int kk = 0; kk < 32; kk += 8) {
            wmma::fragment<wmma::matrix_a, 16, 16, 8, wmma::precision::tf32, wmma::row_major> a0, a1;
            wmma::fragment<wmma::matrix_b, 16, 16, 8, wmma::precision::tf32, wmma::row_major> b0, b1;
            wmma::load_matrix_sync(a0, As + wr * 36 + kk, 36);
            wmma::load_matrix_sync(a1, As + (wr + 16) * 36 + kk, 36);
            wmma::load_matrix_sync(b0, Bs + kk * 68 + wc, 68);
            wmma::load_matrix_sync(b1, Bs + kk * 68 + wc + 16, 68);
            wmma::mma_sync(c[0][0], a0, b0, c[0][0]);
            wmma::mma_sync(c[0][1], a0, b1, c[0][1]);
            wmma::mma_sync(c[1][0], a1, b0, c[1][0]);
            wmma::mma_sync(c[1][1], a1, b1, c[1][1]);
        }
        __syncthreads();
    }

#pragma unroll
    for (int i = 0; i < 2; i++)
#pragma unroll
        for (int j = 0; j < 2; j++)
            wmma::store_matrix_sync(&Cs[wr + i * 16][wc + j * 16], c[i][j], 68, wmma::mem_row_major);
    __syncthreads();

    for (int idx = tid; idx < 128 * 64; idx += 256) {
        int m = idx >> 6, nn = idx & 63;
        if (row0 + m < M) C[(size_t)(row0 + m) * N + col0 + nn] = Cs[m][nn];
    }

    {
        int r = tid >> 1;
        int half = tid & 1;
        float ps = 0.f, pd = 0.f;
#pragma unroll
        for (int cc = 0; cc < 32; cc++) {
            float v = Cs[r][half * 32 + cc];
            ps = fmaf(v, aS[col0 + half * 32 + cc], ps);
            pd = fmaf(v, aD[col0 + half * 32 + cc], pd);
        }
        ps += __shfl_down_sync(0xffffffffu, ps, 1);
        pd += __shfl_down_sync(0xffffffffu, pd, 1);
        if (half == 0 && row0 + r < M) {
            int nh = N >> 6;
            int head = col0 >> 6;
            gas[(row0 + r) * nh + head] = ps;
            gad[(row0 + r) * nh + head] = pd;
        }
    }
}

// ---------------- per-edge weight precompute (warp per node) -------------------
__global__ __launch_bounds__(256) void k_wprep4(
    const float* __restrict__ as, const float* __restrict__ ad, int n)
{
    int warp = threadIdx.x >> 5, lane = threadIdx.x & 31;
    int node = blockIdx.x * 8 + warp;
    if (node >= n) return;
    int beg = g_off[node];
    int deg = g_off[node + 1] - beg;
    float4 adv = *(const float4*)(ad + node * 4);

    float m0 = -1e30f, m1 = -1e30f, m2 = -1e30f, m3 = -1e30f;
    for (int i = lane; i < deg; i += 32) {
        int s = g_srcs[beg + i];
        float4 av = *(const float4*)(as + s * 4);
        m0 = fmaxf(m0, lrelu(av.x + adv.x));
        m1 = fmaxf(m1, lrelu(av.y + adv.y));
        m2 = fmaxf(m2, lrelu(av.z + adv.z));
        m3 = fmaxf(m3, lrelu(av.w + adv.w));
    }
#pragma unroll
    for (int o = 16; o > 0; o >>= 1) {
        m0 = fmaxf(m0, __shfl_xor_sync(0xffffffffu, m0, o));
        m1 = fmaxf(m1, __shfl_xor_sync(0xffffffffu, m1, o));
        m2 = fmaxf(m2, __shfl_xor_sync(0xffffffffu, m2, o));
        m3 = fmaxf(m3, __shfl_xor_sync(0xffffffffu, m3, o));
    }
    float d0 = 0, d1 = 0, d2 = 0, d3 = 0;
    for (int i = lane; i < deg; i += 32) {
        int s = g_srcs[beg + i];
        float4 av = *(const float4*)(as + s * 4);
        float w0 = __expf(lrelu(av.x + adv.x) - m0);
        float w1 = __expf(lrelu(av.y + adv.y) - m1);
        float w2 = __expf(lrelu(av.z + adv.z) - m2);
        float w3 = __expf(lrelu(av.w + adv.w) - m3);
        *(float4*)(g_w + (size_t)(beg + i) * 4) = make_float4(w0, w1, w2, w3);
        d0 += w0; d1 += w1; d2 += w2; d3 += w3;
    }
#pragma unroll
    for (int o = 16; o > 0; o >>= 1) {
        d0 += __shfl_xor_sync(0xffffffffu, d0, o);
        d1 += __shfl_xor_sync(0xffffffffu, d1, o);
        d2 += __shfl_xor_sync(0xffffffffu, d2, o);
        d3 += __shfl_xor_sync(0xffffffffu, d3, o);
    }
    float r0 = 1.f / (d0 + 1e-16f);
    float r1 = 1.f / (d1 + 1e-16f);
    float r2 = 1.f / (d2 + 1e-16f);
    float r3 = 1.f / (d3 + 1e-16f);
    for (int i = lane; i < deg; i += 32) {
        float4 w = *(const float4*)(g_w + (size_t)(beg + i) * 4);
        w.x *= r0; w.y *= r1; w.z *= r2; w.w *= r3;
        *(float4*)(g_w + (size_t)(beg + i) * 4) = w;
    }
}

__global__ __launch_bounds__(256) void k_wprep1(
    const float* __restrict__ as, const float* __restrict__ ad, int n)
{
    int warp = threadIdx.x >> 5, lane = threadIdx.x & 31;
    int node = blockIdx.x * 8 + warp;
    if (node >= n) return;
    int beg = g_off[node];
    int deg = g_off[node + 1] - beg;
    float adv = ad[node];

    float m = -1e30f;
    for (int i = lane; i < deg; i += 32)
        m = fmaxf(m, lrelu(as[g_srcs[beg + i]] + adv));
#pragma unroll
    for (int o = 16; o > 0; o >>= 1)
        m = fmaxf(m, __shfl_xor_sync(0xffffffffu, m, o));
    float d = 0.f;
    for (int i = lane; i < deg; i += 32) {
        float w = __expf(lrelu(as[g_srcs[beg + i]] + adv) - m);
        g_w[beg + i] = w;
        d += w;
    }
#pragma unroll
    for (int o = 16; o > 0; o >>= 1)
        d += __shfl_xor_sync(0xffffffffu, d, o);
    float r = 1.f / (d + 1e-16f);
    for (int i = lane; i < deg; i += 32)
        g_w[beg + i] *= r;
}

// ---------------- GAT aggregation, H=4: 1 node/block, 256 thr, float4 ----------
__global__ __launch_bounds__(256) void k_agg4(
    const float* __restrict__ h, const float* __restrict__ bias,
    float* __restrict__ out, int elu)
{
    __shared__ float4 red[256];
    int n = blockIdx.x, tid = threadIdx.x;
    int sub = tid >> 6;           // edge subgroup 0..3
    int l   = tid & 63;           // feature quad: features 4l..4l+3
    int head = l >> 4;
    int beg = g_off[n];
    int deg = g_off[n + 1] - beg;

    float4 acc = make_float4(0.f, 0.f, 0.f, 0.f);
    int i = sub;
    for (; i + 4 < deg; i += 8) {
        int s0 = g_srcs[beg + i];
        int s1 = g_srcs[beg + i + 4];
        float w0 = g_w[(size_t)(beg + i) * 4 + head];
        float w1 = g_w[(size_t)(beg + i + 4) * 4 + head];
        float4 v0 = *(const float4*)&h[(size_t)s0 * 256 + l * 4];
        float4 v1 = *(const float4*)&h[(size_t)s1 * 256 + l * 4];
        acc.x = fmaf(v0.x, w0, acc.x); acc.y = fmaf(v0.y, w0, acc.y);
        acc.z = fmaf(v0.z, w0, acc.z); acc.w = fmaf(v0.w, w0, acc.w);
        acc.x = fmaf(v1.x, w1, acc.x); acc.y = fmaf(v1.y, w1, acc.y);
        acc.z = fmaf(v1.z, w1, acc.z); acc.w = fmaf(v1.w, w1, acc.w);
    }
    if (i < deg) {
        int s = g_srcs[beg + i];
        float w = g_w[(size_t)(beg + i) * 4 + head];
        float4 v = *(const float4*)&h[(size_t)s * 256 + l * 4];
        acc.x = fmaf(v.x, w, acc.x); acc.y = fmaf(v.y, w, acc.y);
        acc.z = fmaf(v.z, w, acc.z); acc.w = fmaf(v.w, w, acc.w);
    }

    red[tid] = acc;
    __syncthreads();
    if (sub == 0) {
        float4 a1 = red[l + 64], a2 = red[l + 128], a3 = red[l + 192];
        acc.x += a1.x + a2.x + a3.x;
        acc.y += a1.y + a2.y + a3.y;
        acc.z += a1.z + a2.z + a3.z;
        acc.w += a1.w + a2.w + a3.w;
        float4 b = *(const float4*)&bias[l * 4];
        acc.x += b.x; acc.y += b.y; acc.z += b.z; acc.w += b.w;
        if (elu) {
            acc.x = acc.x > 0.f ? acc.x : expm1f(acc.x);
            acc.y = acc.y > 0.f ? acc.y : expm1f(acc.y);
            acc.z = acc.z > 0.f ? acc.z : expm1f(acc.z);
            acc.w = acc.w > 0.f ? acc.w : expm1f(acc.w);
        }
        *(float4*)&out[(size_t)n * 256 + l * 4] = acc;
    }
}

// ---------------- GAT aggregation, H=1, F=64 -----------------------------------
__global__ __launch_bounds__(64) void k_agg1(
    const float* __restrict__ h, const float* __restrict__ bias,
    float* __restrict__ out)
{
    int n = blockIdx.x, f = threadIdx.x;
    int beg = g_off[n];
    int deg = g_off[n + 1] - beg;

    float acc = 0.f;
    int i = 0;
    for (; i + 4 <= deg; i += 4) {
        int s0 = g_srcs[beg + i + 0];
        int s1 = g_srcs[beg + i + 1];
        int s2 = g_srcs[beg + i + 2];
        int s3 = g_srcs[beg + i + 3];
        float w0 = g_w[beg + i + 0];
        float w1 = g_w[beg + i + 1];
        float w2 = g_w[beg + i + 2];
        float w3 = g_w[beg + i + 3];
        acc = fmaf(h[(size_t)s0 * 64 + f], w0, acc);
        acc = fmaf(h[(size_t)s1 * 64 + f], w1, acc);
        acc = fmaf(h[(size_t)s2 * 64 + f], w2, acc);
        acc = fmaf(h[(size_t)s3 * 64 + f], w3, acc);
    }
    for (; i < deg; i++)
        acc = fmaf(h[(size_t)g_srcs[beg + i] * 64 + f], g_w[beg + i], acc);
    out[(size_t)n * 64 + f] = acc + bias[f];
}

// ---------------- mean pool over sorted batch ids -----------------------------
__global__ void k_pool(const float* __restrict__ node, const int* __restrict__ batch,
                       float* __restrict__ gout, int n)
{
    int g = blockIdx.x;
    int lo = 0, hi = n;
    while (lo < hi) { int mid = (lo + hi) >> 1; if (batch[mid] < g) lo = mid + 1; else hi = mid; }
    int start = lo;
    lo = start; hi = n;
    while (lo < hi) { int mid = (lo + hi) >> 1; if (batch[mid] < g + 1) lo = mid + 1; else hi = mid; }
    int end = lo;

    int f = threadIdx.x & 63;
    int sub = threadIdx.x >> 6;
    float acc = 0.f;
    for (int i = start + sub; i < end; i += 4)
        acc += node[(size_t)i * 64 + f];
    __shared__ float s[256];
    s[threadIdx.x] = acc;
    __syncthreads();
    if (threadIdx.x < 64) {
        float v = s[threadIdx.x] + s[threadIdx.x + 64] + s[threadIdx.x + 128] + s[threadIdx.x + 192];
        int cnt = end - start;
        gout[g * 64 + threadIdx.x] = v / (float)max(cnt, 1);
    }
}

// ---------------- host side ----------------------------------------------------
extern "C" void kernel_launch(void* const* d_in, const int* in_sizes, int n_in,
                              void* d_out, int out_size)
{
    const float* x    = (const float*)d_in[0];
    const int*   ei   = (const int*)d_in[1];
    const int*   batch= (const int*)d_in[2];
    const float* W1   = (const float*)d_in[3];
    const float* as1  = (const float*)d_in[4];
    const float* ad1  = (const float*)d_in[5];
    const float* b1   = (const float*)d_in[6];
    const float* W2   = (const float*)d_in[7];
    const float* as2  = (const float*)d_in[8];
    const float* ad2  = (const float*)d_in[9];
    const float* b2   = (const float*)d_in[10];
    const float* W3   = (const float*)d_in[11];
    const float* as3  = (const float*)d_in[12];
    const float* ad3  = (const float*)d_in[13];
    const float* b3   = (const float*)d_in[14];

    int n = in_sizes[0] / 256;
    int E = in_sizes[1] / 2;
    float* out = (float*)d_out;
    int G = (out_size - n * 64) / 64;

    float *p_h, *p_h2, *p_as, *p_ad;
    cudaGetSymbolAddress((void**)&p_h,  g_h);
    cudaGetSymbolAddress((void**)&p_h2, g_h2);
    cudaGetSymbolAddress((void**)&p_as, g_as);
    cudaGetSymbolAddress((void**)&p_ad, g_ad);

    int tot = E + n;
    int nb = (n + 1023) / 1024;
    int nw = (n + 7) / 8;

    dim3 gbig(2, (n + 127) / 128);     // 128x128 tiles, N=256
    dim3 gsm(1, (n + 127) / 128);      // 128x64 tile,  N=64

    // Launch index 3 = layer-1 GEMM so ncu (which profiles launch #3) shows it.
    k_zero<<<(n + 255) / 256, 256>>>(n);                                        // 0
    k_deg<<<(tot + 255) / 256, 256>>>(ei, E, n);                                // 1
    k_part<<<nb, 1024>>>(n);                                                    // 2
    k_gemm128<<<gbig, 256>>>(x, W1, p_h2, as1, ad1, p_as, p_ad, n, 256, 256);   // 3
    k_scanp<<<1, 64>>>(nb);                                                     // 4
    k_offsets<<<nb, 1024>>>(n);                                                 // 5
    k_scatter<<<(tot + 255) / 256, 256>>>(ei, E, n);                            // 6

    // layer 1 (cont.)
    k_wprep4<<<nw, 256>>>(p_as, p_ad, n);
    k_agg4<<<n, 256>>>(p_h2, b1, p_h, 1);
    // layer 2
    k_gemm128<<<gbig, 256>>>(p_h, W2, p_h2, as2, ad2, p_as, p_ad, n, 256, 256);
    k_wprep4<<<nw, 256>>>(p_as, p_ad, n);
    k_agg4<<<n, 256>>>(p_h2, b2, p_h, 1);
    // layer 3
    k_gemm_tc<<<gsm, 256>>>(p_h, W3, p_h2, as3, ad3, p_as, p_ad, n, 64, 256);
    k_wprep1<<<nw, 256>>>(p_as, p_ad, n);
    k_agg1<<<n, 64>>>(p_h2, b3, out);
    // pooling
    k_pool<<<G, 256>>>(out, batch, out + n * 64, n);
}

// round 13
// speedup vs baseline: 1.2395x; 1.2395x over previous
#include <cuda_runtime.h>
#include <cuda_fp16.h>
#include <math.h>
#include <mma.h>
using namespace nvcuda;

#define NMAX 50000
#define EMAX 800000
#define EPMAX (EMAX + NMAX)
#define FH 256
#define NHEADS 4
#define NBPART ((NMAX + 1023) / 1024)

// ---------------- scratch (device globals) ------------------------------------
__device__ float  g_h[NMAX * FH];       // aggregation output (fp32, GEMM input)
__device__ __half g_h2h[NMAX * FH];     // GEMM output (fp16, gather operand only)
__device__ float  g_as[NMAX * NHEADS];  // alpha_src per node
__device__ float  g_ad[NMAX * NHEADS];  // alpha_dst per node
__device__ float  g_w[EPMAX * NHEADS];  // normalized per-edge weights
__device__ int    g_off[NMAX + 1];
__device__ int    g_deg[NMAX];
__device__ int    g_cur[NMAX];
__device__ int    g_srcs[EPMAX];
__device__ int    g_part[NBPART];
__device__ int    g_ppre[NBPART];

__device__ __forceinline__ float lrelu(float x) { return x > 0.f ? x : 0.2f * x; }

// ---------------- CSR build ----------------------------------------------------
__global__ void k_zero(int n) {
    int i = blockIdx.x * blockDim.x + threadIdx.x;
    if (i < n) { g_deg[i] = 0; g_cur[i] = 0; }
}

__global__ void k_deg(const int* __restrict__ ei, int E, int n) {
    int i = blockIdx.x * blockDim.x + threadIdx.x;
    int tot = E + n;
    if (i < tot) {
        int dst = (i < E) ? ei[E + i] : (i - E);
        atomicAdd(&g_deg[dst], 1);
    }
}

__global__ __launch_bounds__(1024) void k_part(int n) {
    __shared__ int s[1024];
    int i = blockIdx.x * 1024 + threadIdx.x;
    s[threadIdx.x] = (i < n) ? g_deg[i] : 0;
    __syncthreads();
    for (int off = 512; off > 0; off >>= 1) {
        if (threadIdx.x < off) s[threadIdx.x] += s[threadIdx.x + off];
        __syncthreads();
    }
    if (threadIdx.x == 0) g_part[blockIdx.x] = s[0];
}

__global__ void k_scanp(int nb) {
    __shared__ int s[64];
    int tid = threadIdx.x;
    s[tid] = (tid < nb) ? g_part[tid] : 0;
    __syncthreads();
    for (int off = 1; off < 64; off <<= 1) {
        int t = (tid >= off) ? s[tid - off] : 0;
        __syncthreads();
        s[tid] += t;
        __syncthreads();
    }
    if (tid < nb) g_ppre[tid] = (tid == 0) ? 0 : s[tid - 1];
}

__global__ __launch_bounds__(1024) void k_offsets(int n) {
    __shared__ int s[1024];
    int b = blockIdx.x;
    int i = b * 1024 + threadIdx.x;
    int v = (i < n) ? g_deg[i] : 0;
    s[threadIdx.x] = v;
    __syncthreads();
    for (int off = 1; off < 1024; off <<= 1) {
        int t = (threadIdx.x >= off) ? s[threadIdx.x - off] : 0;
        __syncthreads();
        s[threadIdx.x] += t;
        __syncthreads();
    }
    if (i < n) g_off[i + 1] = g_ppre[b] + s[threadIdx.x];
    if (b == 0 && threadIdx.x == 0) g_off[0] = 0;
}

__global__ void k_scatter(const int* __restrict__ ei, int E, int n) {
    int i = blockIdx.x * blockDim.x + threadIdx.x;
    int tot = E + n;
    if (i < tot) {
        int src, dst;
        if (i < E) { src = ei[i]; dst = ei[E + i]; }
        else       { src = i - E; dst = src; }
        int pos = g_off[dst] + atomicAdd(&g_cur[dst], 1);
        g_srcs[pos] = src;
    }
}

// ---------------- GEMM: 128x64 block tile (R10-proven), C in fp16, fused alpha -
__global__ __launch_bounds__(256) void k_gemm_tc(
    const float* __restrict__ A, const float* __restrict__ B, __half* __restrict__ C,
    const float* __restrict__ aS, const float* __restrict__ aD,
    float* __restrict__ gas, float* __restrict__ gad,
    int M, int N, int K)
{
    __shared__ float smem[128 * 68];                 // 34816 B
    float* As = smem;                                // [128][36]
    float* Bs = smem + 128 * 36;                     // [32][68]
    float (*Cs)[68] = (float(*)[68])smem;            // epilogue alias [128][68]

    int tid = threadIdx.x;
    int warp = tid >> 5;
    int row0 = blockIdx.y * 128, col0 = blockIdx.x * 64;
    int wr = (warp & 3) * 32;
    int wc = (warp >> 2) * 32;

    wmma::fragment<wmma::accumulator, 16, 16, 8, float> c[2][2];
#pragma unroll
    for (int i = 0; i < 2; i++)
#pragma unroll
        for (int j = 0; j < 2; j++)
            wmma::fill_fragment(c[i][j], 0.f);

    for (int k0 = 0; k0 < K; k0 += 32) {
        // stage A 128x32
#pragma unroll
        for (int r = 0; r < 4; r++) {
            int idx = tid + r * 256;
            int m = idx >> 3;
            int kk = (idx & 7) * 4;
            float4 v = make_float4(0.f, 0.f, 0.f, 0.f);
            if (row0 + m < M) v = *(const float4*)&A[(size_t)(row0 + m) * K + k0 + kk];
            float* p = As + m * 36 + kk;
            p[0] = wmma::__float_to_tf32(v.x);
            p[1] = wmma::__float_to_tf32(v.y);
            p[2] = wmma::__float_to_tf32(v.z);
            p[3] = wmma::__float_to_tf32(v.w);
        }
        // stage B 32x64
#pragma unroll
        for (int r = 0; r < 2; r++) {
            int idx = tid + r * 256;
            int kk = idx >> 4;
            int nn = (idx & 15) * 4;
            float4 v = *(const float4*)&B[(size_t)(k0 + kk) * N + col0 + nn];
            float* p = Bs + kk * 68 + nn;
            p[0] = wmma::__float_to_tf32(v.x);
            p[1] = wmma::__float_to_tf32(v.y);
            p[2] = wmma::__float_to_tf32(v.z);
            p[3] = wmma::__float_to_tf32(v.w);
        }
        __syncthreads();
#pragma unroll
        for (int kk = 0; kk < 32; kk += 8) {
            wmma::fragment<wmma::matrix_a, 16, 16, 8, wmma::precision::tf32, wmma::row_major> a0, a1;
            wmma::fragment<wmma::matrix_b, 16, 16, 8, wmma::precision::tf32, wmma::row_major> b0, b1;
            wmma::load_matrix_sync(a0, As + wr * 36 + kk, 36);
            wmma::load_matrix_sync(a1, As + (wr + 16) * 36 + kk, 36);
            wmma::load_matrix_sync(b0, Bs + kk * 68 + wc, 68);
            wmma::load_matrix_sync(b1, Bs + kk * 68 + wc + 16, 68);
            wmma::mma_sync(c[0][0], a0, b0, c[0][0]);
            wmma::mma_sync(c[0][1], a0, b1, c[0][1]);
            wmma::mma_sync(c[1][0], a1, b0, c[1][0]);
            wmma::mma_sync(c[1][1], a1, b1, c[1][1]);
        }
        __syncthreads();
    }

    // stage C tile (aliases As/Bs, safe after sync)
#pragma unroll
    for (int i = 0; i < 2; i++)
#pragma unroll
        for (int j = 0; j < 2; j++)
            wmma::store_matrix_sync(&Cs[wr + i * 16][wc + j * 16], c[i][j], 68, wmma::mem_row_major);
    __syncthreads();

    // write C as fp16 (gather operand only); __half2 pairs
    for (int idx = tid; idx < 128 * 32; idx += 256) {
        int m = idx >> 5, nn = (idx & 31) * 2;
        if (row0 + m < M) {
            __half2 hv = __floats2half2_rn(Cs[m][nn], Cs[m][nn + 1]);
            *(__half2*)&C[(size_t)(row0 + m) * N + col0 + nn] = hv;
        }
    }

    // fused alpha: 2 threads per row, 32 cols each (from fp32 Cs — full precision)
    {
        int r = tid >> 1;
        int half = tid & 1;
        float ps = 0.f, pd = 0.f;
#pragma unroll
        for (int cc = 0; cc < 32; cc++) {
            float v = Cs[r][half * 32 + cc];
            ps = fmaf(v, aS[col0 + half * 32 + cc], ps);
            pd = fmaf(v, aD[col0 + half * 32 + cc], pd);
        }
        ps += __shfl_down_sync(0xffffffffu, ps, 1);
        pd += __shfl_down_sync(0xffffffffu, pd, 1);
        if (half == 0 && row0 + r < M) {
            int nh = N >> 6;
            int head = col0 >> 6;
            gas[(row0 + r) * nh + head] = ps;
            gad[(row0 + r) * nh + head] = pd;
        }
    }
}

// ---------------- per-edge weight precompute (warp per node) -------------------
__global__ __launch_bounds__(256) void k_wprep4(
    const float* __restrict__ as, const float* __restrict__ ad, int n)
{
    int warp = threadIdx.x >> 5, lane = threadIdx.x & 31;
    int node = blockIdx.x * 8 + warp;
    if (node >= n) return;
    int beg = g_off[node];
    int deg = g_off[node + 1] - beg;
    float4 adv = *(const float4*)(ad + node * 4);

    float m0 = -1e30f, m1 = -1e30f, m2 = -1e30f, m3 = -1e30f;
    for (int i = lane; i < deg; i += 32) {
        int s = g_srcs[beg + i];
        float4 av = *(const float4*)(as + s * 4);
        m0 = fmaxf(m0, lrelu(av.x + adv.x));
        m1 = fmaxf(m1, lrelu(av.y + adv.y));
        m2 = fmaxf(m2, lrelu(av.z + adv.z));
        m3 = fmaxf(m3, lrelu(av.w + adv.w));
    }
#pragma unroll
    for (int o = 16; o > 0; o >>= 1) {
        m0 = fmaxf(m0, __shfl_xor_sync(0xffffffffu, m0, o));
        m1 = fmaxf(m1, __shfl_xor_sync(0xffffffffu, m1, o));
        m2 = fmaxf(m2, __shfl_xor_sync(0xffffffffu, m2, o));
        m3 = fmaxf(m3, __shfl_xor_sync(0xffffffffu, m3, o));
    }
    float d0 = 0, d1 = 0, d2 = 0, d3 = 0;
    for (int i = lane; i < deg; i += 32) {
        int s = g_srcs[beg + i];
        float4 av = *(const float4*)(as + s * 4);
        float w0 = __expf(lrelu(av.x + adv.x) - m0);
        float w1 = __expf(lrelu(av.y + adv.y) - m1);
        float w2 = __expf(lrelu(av.z + adv.z) - m2);
        float w3 = __expf(lrelu(av.w + adv.w) - m3);
        *(float4*)(g_w + (size_t)(beg + i) * 4) = make_float4(w0, w1, w2, w3);
        d0 += w0; d1 += w1; d2 += w2; d3 += w3;
    }
#pragma unroll
    for (int o = 16; o > 0; o >>= 1) {
        d0 += __shfl_xor_sync(0xffffffffu, d0, o);
        d1 += __shfl_xor_sync(0xffffffffu, d1, o);
        d2 += __shfl_xor_sync(0xffffffffu, d2, o);
        d3 += __shfl_xor_sync(0xffffffffu, d3, o);
    }
    float r0 = 1.f / (d0 + 1e-16f);
    float r1 = 1.f / (d1 + 1e-16f);
    float r2 = 1.f / (d2 + 1e-16f);
    float r3 = 1.f / (d3 + 1e-16f);
    for (int i = lane; i < deg; i += 32) {
        float4 w = *(const float4*)(g_w + (size_t)(beg + i) * 4);
        w.x *= r0; w.y *= r1; w.z *= r2; w.w *= r3;
        *(float4*)(g_w + (size_t)(beg + i) * 4) = w;
    }
}

__global__ __launch_bounds__(256) void k_wprep1(
    const float* __restrict__ as, const float* __restrict__ ad, int n)
{
    int warp = threadIdx.x >> 5, lane = threadIdx.x & 31;
    int node = blockIdx.x * 8 + warp;
    if (node >= n) return;
    int beg = g_off[node];
    int deg = g_off[node + 1] - beg;
    float adv = ad[node];

    float m = -1e30f;
    for (int i = lane; i < deg; i += 32)
        m = fmaxf(m, lrelu(as[g_srcs[beg + i]] + adv));
#pragma unroll
    for (int o = 16; o > 0; o >>= 1)
        m = fmaxf(m, __shfl_xor_sync(0xffffffffu, m, o));
    float d = 0.f;
    for (int i = lane; i < deg; i += 32) {
        float w = __expf(lrelu(as[g_srcs[beg + i]] + adv) - m);
        g_w[beg + i] = w;
        d += w;
    }
#pragma unroll
    for (int o = 16; o > 0; o >>= 1)
        d += __shfl_xor_sync(0xffffffffu, d, o);
    float r = 1.f / (d + 1e-16f);
    for (int i = lane; i < deg; i += 32)
        g_w[beg + i] *= r;
}

// ---------------- GAT aggregation, H=4: fp16 gather, fp32 accumulate -----------
// 1 node/block, 256 thr, 4 edge-subgroups x 64 feature-lanes; 8B loads (4 halfs).
__global__ __launch_bounds__(256) void k_agg4(
    const __half* __restrict__ h, const float* __restrict__ bias,
    float* __restrict__ out, int elu)
{
    __shared__ float4 red[256];
    int n = blockIdx.x, tid = threadIdx.x;
    int sub = tid >> 6;           // edge subgroup 0..3
    int l   = tid & 63;           // feature quad: features 4l..4l+3
    int head = l >> 4;
    int beg = g_off[n];
    int deg = g_off[n + 1] - beg;

    float4 acc = make_float4(0.f, 0.f, 0.f, 0.f);
    int i = sub;
    for (; i + 4 < deg; i += 8) {
        int s0 = g_srcs[beg + i];
        int s1 = g_srcs[beg + i + 4];
        float w0 = g_w[(size_t)(beg + i) * 4 + head];
        float w1 = g_w[(size_t)(beg + i + 4) * 4 + head];
        uint2 r0 = *(const uint2*)&h[(size_t)s0 * 256 + l * 4];
        uint2 r1 = *(const uint2*)&h[(size_t)s1 * 256 + l * 4];
        float2 a0 = __half22float2(*(__half2*)&r0.x);
        float2 b0 = __half22float2(*(__half2*)&r0.y);
        float2 a1 = __half22float2(*(__half2*)&r1.x);
        float2 b1 = __half22float2(*(__half2*)&r1.y);
        acc.x = fmaf(a0.x, w0, acc.x); acc.y = fmaf(a0.y, w0, acc.y);
        acc.z = fmaf(b0.x, w0, acc.z); acc.w = fmaf(b0.y, w0, acc.w);
        acc.x = fmaf(a1.x, w1, acc.x); acc.y = fmaf(a1.y, w1, acc.y);
        acc.z = fmaf(b1.x, w1, acc.z); acc.w = fmaf(b1.y, w1, acc.w);
    }
    if (i < deg) {
        int s = g_srcs[beg + i];
        float w = g_w[(size_t)(beg + i) * 4 + head];
        uint2 r0 = *(const uint2*)&h[(size_t)s * 256 + l * 4];
        float2 a0 = __half22float2(*(__half2*)&r0.x);
        float2 b0 = __half22float2(*(__half2*)&r0.y);
        acc.x = fmaf(a0.x, w, acc.x); acc.y = fmaf(a0.y, w, acc.y);
        acc.z = fmaf(b0.x, w, acc.z); acc.w = fmaf(b0.y, w, acc.w);
    }

    red[tid] = acc;
    __syncthreads();
    if (sub == 0) {
        float4 a1 = red[l + 64], a2 = red[l + 128], a3 = red[l + 192];
        acc.x += a1.x + a2.x + a3.x;
        acc.y += a1.y + a2.y + a3.y;
        acc.z += a1.z + a2.z + a3.z;
        acc.w += a1.w + a2.w + a3.w;
        float4 b = *(const float4*)&bias[l * 4];
        acc.x += b.x; acc.y += b.y; acc.z += b.z; acc.w += b.w;
        if (elu) {
            acc.x = acc.x > 0.f ? acc.x : expm1f(acc.x);
            acc.y = acc.y > 0.f ? acc.y : expm1f(acc.y);
            acc.z = acc.z > 0.f ? acc.z : expm1f(acc.z);
            acc.w = acc.w > 0.f ? acc.w : expm1f(acc.w);
        }
        *(float4*)&out[(size_t)n * 256 + l * 4] = acc;
    }
}

// ---------------- GAT aggregation, H=1, F=64: fp16 gather ----------------------
__global__ __launch_bounds__(64) void k_agg1(
    const __half* __restrict__ h, const float* __restrict__ bias,
    float* __restrict__ out)
{
    int n = blockIdx.x, f = threadIdx.x;
    int beg = g_off[n];
    int deg = g_off[n + 1] - beg;

    float acc = 0.f;
    int i = 0;
    for (; i + 4 <= deg; i += 4) {
        int s0 = g_srcs[beg + i + 0];
        int s1 = g_srcs[beg + i + 1];
        int s2 = g_srcs[beg + i + 2];
        int s3 = g_srcs[beg + i + 3];
        float w0 = g_w[beg + i + 0];
        float w1 = g_w[beg + i + 1];
        float w2 = g_w[beg + i + 2];
        float w3 = g_w[beg + i + 3];
        acc = fmaf(__half2float(h[(size_t)s0 * 64 + f]), w0, acc);
        acc = fmaf(__half2float(h[(size_t)s1 * 64 + f]), w1, acc);
        acc = fmaf(__half2float(h[(size_t)s2 * 64 + f]), w2, acc);
        acc = fmaf(__half2float(h[(size_t)s3 * 64 + f]), w3, acc);
    }
    for (; i < deg; i++)
        acc = fmaf(__half2float(h[(size_t)g_srcs[beg + i] * 64 + f]), g_w[beg + i], acc);
    out[(size_t)n * 64 + f] = acc + bias[f];
}

// ---------------- mean pool over sorted batch ids -----------------------------
__global__ void k_pool(const float* __restrict__ node, const int* __restrict__ batch,
                       float* __restrict__ gout, int n)
{
    int g = blockIdx.x;
    int lo = 0, hi = n;
    while (lo < hi) { int mid = (lo + hi) >> 1; if (batch[mid] < g) lo = mid + 1; else hi = mid; }
    int start = lo;
    lo = start; hi = n;
    while (lo < hi) { int mid = (lo + hi) >> 1; if (batch[mid] < g + 1) lo = mid + 1; else hi = mid; }
    int end = lo;

    int f = threadIdx.x & 63;
    int sub = threadIdx.x >> 6;
    float acc = 0.f;
    for (int i = start + sub; i < end; i += 4)
        acc += node[(size_t)i * 64 + f];
    __shared__ float s[256];
    s[threadIdx.x] = acc;
    __syncthreads();
    if (threadIdx.x < 64) {
        float v = s[threadIdx.x] + s[threadIdx.x + 64] + s[threadIdx.x + 128] + s[threadIdx.x + 192];
        int cnt = end - start;
        gout[g * 64 + threadIdx.x] = v / (float)max(cnt, 1);
    }
}

// ---------------- host side ----------------------------------------------------
extern "C" void kernel_launch(void* const* d_in, const int* in_sizes, int n_in,
                              void* d_out, int out_size)
{
    const float* x    = (const float*)d_in[0];
    const int*   ei   = (const int*)d_in[1];
    const int*   batch= (const int*)d_in[2];
    const float* W1   = (const float*)d_in[3];
    const float* as1  = (const float*)d_in[4];
    const float* ad1  = (const float*)d_in[5];
    const float* b1   = (const float*)d_in[6];
    const float* W2   = (const float*)d_in[7];
    const float* as2  = (const float*)d_in[8];
    const float* ad2  = (const float*)d_in[9];
    const float* b2   = (const float*)d_in[10];
    const float* W3   = (const float*)d_in[11];
    const float* as3  = (const float*)d_in[12];
    const float* ad3  = (const float*)d_in[13];
    const float* b3   = (const float*)d_in[14];

    int n = in_sizes[0] / 256;
    int E = in_sizes[1] / 2;
    float* out = (float*)d_out;
    int G = (out_size - n * 64) / 64;

    float *p_h, *p_as, *p_ad;
    __half* p_h2;
    cudaGetSymbolAddress((void**)&p_h,  g_h);
    cudaGetSymbolAddress((void**)&p_h2, g_h2h);
    cudaGetSymbolAddress((void**)&p_as, g_as);
    cudaGetSymbolAddress((void**)&p_ad, g_ad);

    int tot = E + n;
    int nb = (n + 1023) / 1024;
    int nw = (n + 7) / 8;

    dim3 gbig(4, (n + 127) / 128);     // 128x64 tiles, N=256
    dim3 gsm(1, (n + 127) / 128);      // 128x64 tile,  N=64

    // Launch index 3 = layer-1 GEMM so ncu (which profiles launch #3) shows it.
    k_zero<<<(n + 255) / 256, 256>>>(n);                                        // 0
    k_deg<<<(tot + 255) / 256, 256>>>(ei, E, n);                                // 1
    k_part<<<nb, 1024>>>(n);                                                    // 2
    k_gemm_tc<<<gbig, 256>>>(x, W1, p_h2, as1, ad1, p_as, p_ad, n, 256, 256);   // 3
    k_scanp<<<1, 64>>>(nb);                                                     // 4
    k_offsets<<<nb, 1024>>>(n);                                                 // 5
    k_scatter<<<(tot + 255) / 256, 256>>>(ei, E, n);                            // 6

    // layer 1 (cont.)
    k_wprep4<<<nw, 256>>>(p_as, p_ad, n);
    k_agg4<<<n, 256>>>(p_h2, b1, p_h, 1);
    // layer 2
    k_gemm_tc<<<gbig, 256>>>(p_h, W2, p_h2, as2, ad2, p_as, p_ad, n, 256, 256);
    k_wprep4<<<nw, 256>>>(p_as, p_ad, n);
    k_agg4<<<n, 256>>>(p_h2, b2, p_h, 1);
    // layer 3
    k_gemm_tc<<<gsm, 256>>>(p_h, W3, p_h2, as3, ad3, p_as, p_ad, n, 64, 256);
    k_wprep1<<<nw, 256>>>(p_as, p_ad, n);
    k_agg1<<<n, 64>>>(p_h2, b3, out);
    // pooling
    k_pool<<<G, 256>>>(out, batch, out + n * 64, n);
}

// round 14
// speedup vs baseline: 1.5588x; 1.2576x over previous
#include <cuda_runtime.h>
#include <cuda_fp16.h>
#include <math.h>
#include <mma.h>
using namespace nvcuda;

#define NMAX 50000
#define EMAX 800000
#define EPMAX (EMAX + NMAX)
#define FH 256
#define NHEADS 4
#define NBPART ((NMAX + 1023) / 1024)

// ---------------- scratch (device globals) ------------------------------------
__device__ float  g_h[NMAX * FH];       // aggregation output (fp32, GEMM input)
__device__ __half g_h2h[NMAX * FH];     // GEMM output (fp16, gather operand only)
__device__ float  g_as[NMAX * NHEADS];  // alpha_src per node
__device__ float  g_ad[NMAX * NHEADS];  // alpha_dst per node
__device__ float  g_w[EPMAX * NHEADS];  // normalized per-edge weights
__device__ int    g_off[NMAX + 1];
__device__ int    g_deg[NMAX];
__device__ int    g_cur[NMAX];
__device__ int    g_srcs[EPMAX];
__device__ int    g_part[NBPART];
__device__ int    g_ppre[NBPART];

__device__ __forceinline__ float lrelu(float x) { return x > 0.f ? x : 0.2f * x; }

// ---------------- CSR build ----------------------------------------------------
__global__ void k_zero(int n) {
    int i = blockIdx.x * blockDim.x + threadIdx.x;
    if (i < n) { g_deg[i] = 0; g_cur[i] = 0; }
}

__global__ void k_deg(const int* __restrict__ ei, int E, int n) {
    int i = blockIdx.x * blockDim.x + threadIdx.x;
    int tot = E + n;
    if (i < tot) {
        int dst = (i < E) ? ei[E + i] : (i - E);
        atomicAdd(&g_deg[dst], 1);
    }
}

__global__ __launch_bounds__(1024) void k_part(int n) {
    __shared__ int s[1024];
    int i = blockIdx.x * 1024 + threadIdx.x;
    s[threadIdx.x] = (i < n) ? g_deg[i] : 0;
    __syncthreads();
    for (int off = 512; off > 0; off >>= 1) {
        if (threadIdx.x < off) s[threadIdx.x] += s[threadIdx.x + off];
        __syncthreads();
    }
    if (threadIdx.x == 0) g_part[blockIdx.x] = s[0];
}

__global__ void k_scanp(int nb) {
    __shared__ int s[64];
    int tid = threadIdx.x;
    s[tid] = (tid < nb) ? g_part[tid] : 0;
    __syncthreads();
    for (int off = 1; off < 64; off <<= 1) {
        int t = (tid >= off) ? s[tid - off] : 0;
        __syncthreads();
        s[tid] += t;
        __syncthreads();
    }
    if (tid < nb) g_ppre[tid] = (tid == 0) ? 0 : s[tid - 1];
}

__global__ __launch_bounds__(1024) void k_offsets(int n) {
    __shared__ int s[1024];
    int b = blockIdx.x;
    int i = b * 1024 + threadIdx.x;
    int v = (i < n) ? g_deg[i] : 0;
    s[threadIdx.x] = v;
    __syncthreads();
    for (int off = 1; off < 1024; off <<= 1) {
        int t = (threadIdx.x >= off) ? s[threadIdx.x - off] : 0;
        __syncthreads();
        s[threadIdx.x] += t;
        __syncthreads();
    }
    if (i < n) g_off[i + 1] = g_ppre[b] + s[threadIdx.x];
    if (b == 0 && threadIdx.x == 0) g_off[0] = 0;
}

__global__ void k_scatter(const int* __restrict__ ei, int E, int n) {
    int i = blockIdx.x * blockDim.x + threadIdx.x;
    int tot = E + n;
    if (i < tot) {
        int src, dst;
        if (i < E) { src = ei[i]; dst = ei[E + i]; }
        else       { src = i - E; dst = src; }
        int pos = g_off[dst] + atomicAdd(&g_cur[dst], 1);
        g_srcs[pos] = src;
    }
}

// ---------------- GEMM: 128x64 tile, fp16 HMMA (fp32 accum), fused alpha -------
__global__ __launch_bounds__(256) void k_gemm_tc(
    const float* __restrict__ A, const float* __restrict__ B, __half* __restrict__ C,
    const float* __restrict__ aS, const float* __restrict__ aD,
    float* __restrict__ gas, float* __restrict__ gad,
    int M, int N, int K)
{
    __shared__ float smem[128 * 68];                 // 34816 B (epilogue Cs)
    __half* Ash = (__half*)smem;                     // [128][40] halfs = 10240 B
    __half* Bsh = (__half*)(smem + 128 * 40 / 2);    // [32][72]  halfs = 4608 B
    float (*Cs)[68] = (float(*)[68])smem;            // epilogue alias

    int tid = threadIdx.x;
    int warp = tid >> 5;
    int row0 = blockIdx.y * 128, col0 = blockIdx.x * 64;
    int wr = (warp & 3) * 32;
    int wc = (warp >> 2) * 32;

    wmma::fragment<wmma::accumulator, 16, 16, 16, float> c[2][2];
#pragma unroll
    for (int i = 0; i < 2; i++)
#pragma unroll
        for (int j = 0; j < 2; j++)
            wmma::fill_fragment(c[i][j], 0.f);

    for (int k0 = 0; k0 < K; k0 += 32) {
        // stage A 128x32 -> fp16
#pragma unroll
        for (int r = 0; r < 4; r++) {
            int idx = tid + r * 256;
            int m = idx >> 3;
            int kk = (idx & 7) * 4;
            float4 v = make_float4(0.f, 0.f, 0.f, 0.f);
            if (row0 + m < M) v = *(const float4*)&A[(size_t)(row0 + m) * K + k0 + kk];
            __half* p = Ash + m * 40 + kk;
            *(__half2*)(p + 0) = __floats2half2_rn(v.x, v.y);
            *(__half2*)(p + 2) = __floats2half2_rn(v.z, v.w);
        }
        // stage B 32x64 -> fp16
#pragma unroll
        for (int r = 0; r < 2; r++) {
            int idx = tid + r * 256;
            int kk = idx >> 4;
            int nn = (idx & 15) * 4;
            float4 v = *(const float4*)&B[(size_t)(k0 + kk) * N + col0 + nn];
            __half* p = Bsh + kk * 72 + nn;
            *(__half2*)(p + 0) = __floats2half2_rn(v.x, v.y);
            *(__half2*)(p + 2) = __floats2half2_rn(v.z, v.w);
        }
        __syncthreads();
#pragma unroll
        for (int kk = 0; kk < 32; kk += 16) {
            wmma::fragment<wmma::matrix_a, 16, 16, 16, __half, wmma::row_major> a0, a1;
            wmma::fragment<wmma::matrix_b, 16, 16, 16, __half, wmma::row_major> b0, b1;
            wmma::load_matrix_sync(a0, Ash + wr * 40 + kk, 40);
            wmma::load_matrix_sync(a1, Ash + (wr + 16) * 40 + kk, 40);
            wmma::load_matrix_sync(b0, Bsh + kk * 72 + wc, 72);
            wmma::load_matrix_sync(b1, Bsh + kk * 72 + wc + 16, 72);
            wmma::mma_sync(c[0][0], a0, b0, c[0][0]);
            wmma::mma_sync(c[0][1], a0, b1, c[0][1]);
            wmma::mma_sync(c[1][0], a1, b0, c[1][0]);
            wmma::mma_sync(c[1][1], a1, b1, c[1][1]);
        }
        __syncthreads();
    }

    // stage C tile in fp32 smem (aliases staging, safe after sync)
#pragma unroll
    for (int i = 0; i < 2; i++)
#pragma unroll
        for (int j = 0; j < 2; j++)
            wmma::store_matrix_sync(&Cs[wr + i * 16][wc + j * 16], c[i][j], 68, wmma::mem_row_major);
    __syncthreads();

    // write C as fp16 (gather operand only)
    for (int idx = tid; idx < 128 * 32; idx += 256) {
        int m = idx >> 5, nn = (idx & 31) * 2;
        if (row0 + m < M) {
            __half2 hv = __floats2half2_rn(Cs[m][nn], Cs[m][nn + 1]);
            *(__half2*)&C[(size_t)(row0 + m) * N + col0 + nn] = hv;
        }
    }

    // fused alpha: 2 threads per row, 32 cols each (fp32)
    {
        int r = tid >> 1;
        int half = tid & 1;
        float ps = 0.f, pd = 0.f;
#pragma unroll
        for (int cc = 0; cc < 32; cc++) {
            float v = Cs[r][half * 32 + cc];
            ps = fmaf(v, aS[col0 + half * 32 + cc], ps);
            pd = fmaf(v, aD[col0 + half * 32 + cc], pd);
        }
        ps += __shfl_down_sync(0xffffffffu, ps, 1);
        pd += __shfl_down_sync(0xffffffffu, pd, 1);
        if (half == 0 && row0 + r < M) {
            int nh = N >> 6;
            int head = col0 >> 6;
            gas[(row0 + r) * nh + head] = ps;
            gad[(row0 + r) * nh + head] = pd;
        }
    }
}

// ---------------- per-edge weight precompute (warp per node) -------------------
__global__ __launch_bounds__(256) void k_wprep4(
    const float* __restrict__ as, const float* __restrict__ ad, int n)
{
    int warp = threadIdx.x >> 5, lane = threadIdx.x & 31;
    int node = blockIdx.x * 8 + warp;
    if (node >= n) return;
    int beg = g_off[node];
    int deg = g_off[node + 1] - beg;
    float4 adv = *(const float4*)(ad + node * 4);

    float m0 = -1e30f, m1 = -1e30f, m2 = -1e30f, m3 = -1e30f;
    for (int i = lane; i < deg; i += 32) {
        int s = g_srcs[beg + i];
        float4 av = *(const float4*)(as + s * 4);
        m0 = fmaxf(m0, lrelu(av.x + adv.x));
        m1 = fmaxf(m1, lrelu(av.y + adv.y));
        m2 = fmaxf(m2, lrelu(av.z + adv.z));
        m3 = fmaxf(m3, lrelu(av.w + adv.w));
    }
#pragma unroll
    for (int o = 16; o > 0; o >>= 1) {
        m0 = fmaxf(m0, __shfl_xor_sync(0xffffffffu, m0, o));
        m1 = fmaxf(m1, __shfl_xor_sync(0xffffffffu, m1, o));
        m2 = fmaxf(m2, __shfl_xor_sync(0xffffffffu, m2, o));
        m3 = fmaxf(m3, __shfl_xor_sync(0xffffffffu, m3, o));
    }
    float d0 = 0, d1 = 0, d2 = 0, d3 = 0;
    for (int i = lane; i < deg; i += 32) {
        int s = g_srcs[beg + i];
        float4 av = *(const float4*)(as + s * 4);
        float w0 = __expf(lrelu(av.x + adv.x) - m0);
        float w1 = __expf(lrelu(av.y + adv.y) - m1);
        float w2 = __expf(lrelu(av.z + adv.z) - m2);
        float w3 = __expf(lrelu(av.w + adv.w) - m3);
        *(float4*)(g_w + (size_t)(beg + i) * 4) = make_float4(w0, w1, w2, w3);
        d0 += w0; d1 += w1; d2 += w2; d3 += w3;
    }
#pragma unroll
    for (int o = 16; o > 0; o >>= 1) {
        d0 += __shfl_xor_sync(0xffffffffu, d0, o);
        d1 += __shfl_xor_sync(0xffffffffu, d1, o);
        d2 += __shfl_xor_sync(0xffffffffu, d2, o);
        d3 += __shfl_xor_sync(0xffffffffu, d3, o);
    }
    float r0 = 1.f / (d0 + 1e-16f);
    float r1 = 1.f / (d1 + 1e-16f);
    float r2 = 1.f / (d2 + 1e-16f);
    float r3 = 1.f / (d3 + 1e-16f);
    for (int i = lane; i < deg; i += 32) {
        float4 w = *(const float4*)(g_w + (size_t)(beg + i) * 4);
        w.x *= r0; w.y *= r1; w.z *= r2; w.w *= r3;
        *(float4*)(g_w + (size_t)(beg + i) * 4) = w;
    }
}

__global__ __launch_bounds__(256) void k_wprep1(
    const float* __restrict__ as, const float* __restrict__ ad, int n)
{
    int warp = threadIdx.x >> 5, lane = threadIdx.x & 31;
    int node = blockIdx.x * 8 + warp;
    if (node >= n) return;
    int beg = g_off[node];
    int deg = g_off[node + 1] - beg;
    float adv = ad[node];

    float m = -1e30f;
    for (int i = lane; i < deg; i += 32)
        m = fmaxf(m, lrelu(as[g_srcs[beg + i]] + adv));
#pragma unroll
    for (int o = 16; o > 0; o >>= 1)
        m = fmaxf(m, __shfl_xor_sync(0xffffffffu, m, o));
    float d = 0.f;
    for (int i = lane; i < deg; i += 32) {
        float w = __expf(lrelu(as[g_srcs[beg + i]] + adv) - m);
        g_w[beg + i] = w;
        d += w;
    }
#pragma unroll
    for (int o = 16; o > 0; o >>= 1)
        d += __shfl_xor_sync(0xffffffffu, d, o);
    float r = 1.f / (d + 1e-16f);
    for (int i = lane; i < deg; i += 32)
        g_w[beg + i] *= r;
}

// ---------------- GAT aggregation, H=4: fp16 gather, fp32 accumulate -----------
__global__ __launch_bounds__(256) void k_agg4(
    const __half* __restrict__ h, const float* __restrict__ bias,
    float* __restrict__ out, int elu)
{
    __shared__ float4 red[256];
    int n = blockIdx.x, tid = threadIdx.x;
    int sub = tid >> 6;           // edge subgroup 0..3
    int l   = tid & 63;           // feature quad: features 4l..4l+3
    int head = l >> 4;
    int beg = g_off[n];
    int deg = g_off[n + 1] - beg;

    float4 acc = make_float4(0.f, 0.f, 0.f, 0.f);
    int i = sub;
    for (; i + 4 < deg; i += 8) {
        int s0 = g_srcs[beg + i];
        int s1 = g_srcs[beg + i + 4];
        float w0 = g_w[(size_t)(beg + i) * 4 + head];
        float w1 = g_w[(size_t)(beg + i + 4) * 4 + head];
        uint2 r0 = *(const uint2*)&h[(size_t)s0 * 256 + l * 4];
        uint2 r1 = *(const uint2*)&h[(size_t)s1 * 256 + l * 4];
        float2 a0 = __half22float2(*(__half2*)&r0.x);
        float2 b0 = __half22float2(*(__half2*)&r0.y);
        float2 a1 = __half22float2(*(__half2*)&r1.x);
        float2 b1 = __half22float2(*(__half2*)&r1.y);
        acc.x = fmaf(a0.x, w0, acc.x); acc.y = fmaf(a0.y, w0, acc.y);
        acc.z = fmaf(b0.x, w0, acc.z); acc.w = fmaf(b0.y, w0, acc.w);
        acc.x = fmaf(a1.x, w1, acc.x); acc.y = fmaf(a1.y, w1, acc.y);
        acc.z = fmaf(b1.x, w1, acc.z); acc.w = fmaf(b1.y, w1, acc.w);
    }
    if (i < deg) {
        int s = g_srcs[beg + i];
        float w = g_w[(size_t)(beg + i) * 4 + head];
        uint2 r0 = *(const uint2*)&h[(size_t)s * 256 + l * 4];
        float2 a0 = __half22float2(*(__half2*)&r0.x);
        float2 b0 = __half22float2(*(__half2*)&r0.y);
        acc.x = fmaf(a0.x, w, acc.x); acc.y = fmaf(a0.y, w, acc.y);
        acc.z = fmaf(b0.x, w, acc.z); acc.w = fmaf(b0.y, w, acc.w);
    }

    red[tid] = acc;
    __syncthreads();
    if (sub == 0) {
        float4 a1 = red[l + 64], a2 = red[l + 128], a3 = red[l + 192];
        acc.x += a1.x + a2.x + a3.x;
        acc.y += a1.y + a2.y + a3.y;
        acc.z += a1.z + a2.z + a3.z;
        acc.w += a1.w + a2.w + a3.w;
        float4 b = *(const float4*)&bias[l * 4];
        acc.x += b.x; acc.y += b.y; acc.z += b.z; acc.w += b.w;
        if (elu) {
            acc.x = acc.x > 0.f ? acc.x : expm1f(acc.x);
            acc.y = acc.y > 0.f ? acc.y : expm1f(acc.y);
            acc.z = acc.z > 0.f ? acc.z : expm1f(acc.z);
            acc.w = acc.w > 0.f ? acc.w : expm1f(acc.w);
        }
        *(float4*)&out[(size_t)n * 256 + l * 4] = acc;
    }
}

// ---------------- GAT aggregation, H=1, F=64: fp16 gather ----------------------
__global__ __launch_bounds__(64) void k_agg1(
    const __half* __restrict__ h, const float* __restrict__ bias,
    float* __restrict__ out)
{
    int n = blockIdx.x, f = threadIdx.x;
    int beg = g_off[n];
    int deg = g_off[n + 1] - beg;

    float acc = 0.f;
    int i = 0;
    for (; i + 4 <= deg; i += 4) {
        int s0 = g_srcs[beg + i + 0];
        int s1 = g_srcs[beg + i + 1];
        int s2 = g_srcs[beg + i + 2];
        int s3 = g_srcs[beg + i + 3];
        float w0 = g_w[beg + i + 0];
        float w1 = g_w[beg + i + 1];
        float w2 = g_w[beg + i + 2];
        float w3 = g_w[beg + i + 3];
        acc = fmaf(__half2float(h[(size_t)s0 * 64 + f]), w0, acc);
        acc = fmaf(__half2float(h[(size_t)s1 * 64 + f]), w1, acc);
        acc = fmaf(__half2float(h[(size_t)s2 * 64 + f]), w2, acc);
        acc = fmaf(__half2float(h[(size_t)s3 * 64 + f]), w3, acc);
    }
    for (; i < deg; i++)
        acc = fmaf(__half2float(h[(size_t)g_srcs[beg + i] * 64 + f]), g_w[beg + i], acc);
    out[(size_t)n * 64 + f] = acc + bias[f];
}

// ---------------- mean pool over sorted batch ids -----------------------------
__global__ void k_pool(const float* __restrict__ node, const int* __restrict__ batch,
                       float* __restrict__ gout, int n)
{
    int g = blockIdx.x;
    int lo = 0, hi = n;
    while (lo < hi) { int mid = (lo + hi) >> 1; if (batch[mid] < g) lo = mid + 1; else hi = mid; }
    int start = lo;
    lo = start; hi = n;
    while (lo < hi) { int mid = (lo + hi) >> 1; if (batch[mid] < g + 1) lo = mid + 1; else hi = mid; }
    int end = lo;

    int f = threadIdx.x & 63;
    int sub = threadIdx.x >> 6;
    float acc = 0.f;
    for (int i = start + sub; i < end; i += 4)
        acc += node[(size_t)i * 64 + f];
    __shared__ float s[256];
    s[threadIdx.x] = acc;
    __syncthreads();
    if (threadIdx.x < 64) {
        float v = s[threadIdx.x] + s[threadIdx.x + 64] + s[threadIdx.x + 128] + s[threadIdx.x + 192];
        int cnt = end - start;
        gout[g * 64 + threadIdx.x] = v / (float)max(cnt, 1);
    }
}

// ---------------- host side ----------------------------------------------------
extern "C" void kernel_launch(void* const* d_in, const int* in_sizes, int n_in,
                              void* d_out, int out_size)
{
    const float* x    = (const float*)d_in[0];
    const int*   ei   = (const int*)d_in[1];
    const int*   batch= (const int*)d_in[2];
    const float* W1   = (const float*)d_in[3];
    const float* as1  = (const float*)d_in[4];
    const float* ad1  = (const float*)d_in[5];
    const float* b1   = (const float*)d_in[6];
    const float* W2   = (const float*)d_in[7];
    const float* as2  = (const float*)d_in[8];
    const float* ad2  = (const float*)d_in[9];
    const float* b2   = (const float*)d_in[10];
    const float* W3   = (const float*)d_in[11];
    const float* as3  = (const float*)d_in[12];
    const float* ad3  = (const float*)d_in[13];
    const float* b3   = (const float*)d_in[14];

    int n = in_sizes[0] / 256;
    int E = in_sizes[1] / 2;
    float* out = (float*)d_out;
    int G = (out_size - n * 64) / 64;

    float *p_h, *p_as, *p_ad;
    __half* p_h2;
    cudaGetSymbolAddress((void**)&p_h,  g_h);
    cudaGetSymbolAddress((void**)&p_h2, g_h2h);
    cudaGetSymbolAddress((void**)&p_as, g_as);
    cudaGetSymbolAddress((void**)&p_ad, g_ad);

    int tot = E + n;
    int nb = (n + 1023) / 1024;
    int nw = (n + 7) / 8;

    dim3 gbig(4, (n + 127) / 128);     // 128x64 tiles, N=256
    dim3 gsm(1, (n + 127) / 128);      // 128x64 tile,  N=64

    // Launch index 3 = layer-1 GEMM so ncu (which profiles launch #3) shows it.
    k_zero<<<(n + 255) / 256, 256>>>(n);                                        // 0
    k_deg<<<(tot + 255) / 256, 256>>>(ei, E, n);                                // 1
    k_part<<<nb, 1024>>>(n);                                                    // 2
    k_gemm_tc<<<gbig, 256>>>(x, W1, p_h2, as1, ad1, p_as, p_ad, n, 256, 256);   // 3
    k_scanp<<<1, 64>>>(nb);                                                     // 4
    k_offsets<<<nb, 1024>>>(n);                                                 // 5
    k_scatter<<<(tot + 255) / 256, 256>>>(ei, E, n);                            // 6

    // layer 1 (cont.)
    k_wprep4<<<nw, 256>>>(p_as, p_ad, n);
    k_agg4<<<n, 256>>>(p_h2, b1, p_h, 1);
    // layer 2
    k_gemm_tc<<<gbig, 256>>>(p_h, W2, p_h2, as2, ad2, p_as, p_ad, n, 256, 256);
    k_wprep4<<<nw, 256>>>(p_as, p_ad, n);
    k_agg4<<<n, 256>>>(p_h2, b2, p_h, 1);
    // layer 3
    k_gemm_tc<<<gsm, 256>>>(p_h, W3, p_h2, as3, ad3, p_as, p_ad, n, 64, 256);
    k_wprep1<<<nw, 256>>>(p_as, p_ad, n);
    k_agg1<<<n, 64>>>(p_h2, b3, out);
    // pooling
    k_pool<<<G, 256>>>(out, batch, out + n * 64, n);
}

// round 16
// speedup vs baseline: 1.7482x; 1.1215x over previous
#include <cuda_runtime.h>
#include <cuda_fp16.h>
#include <math.h>
#include <mma.h>
using namespace nvcuda;

#define NMAX 50000
#define EMAX 800000
#define EPMAX (EMAX + NMAX)
#define FH 256
#define NHEADS 4
#define NBPART ((NMAX + 1023) / 1024)

// ---------------- scratch (device globals) ------------------------------------
__device__ __half g_xh[NMAX * FH];      // fp16 copy of input x
__device__ __half g_h[NMAX * FH];       // aggregation output (fp16)
__device__ __half g_h2h[NMAX * FH];     // GEMM output (fp16, gather operand)
__device__ float  g_as[NMAX * NHEADS];  // alpha_src per node
__device__ float  g_ad[NMAX * NHEADS];  // alpha_dst per node
__device__ float  g_w[EPMAX * NHEADS];  // normalized per-edge weights
__device__ int    g_off[NMAX + 1];
__device__ int    g_deg[NMAX];
__device__ int    g_cur[NMAX];
__device__ int    g_srcs[EPMAX];
__device__ int    g_part[NBPART];
__device__ int    g_ppre[NBPART];

__device__ __forceinline__ float lrelu(float x) { return x > 0.f ? x : 0.2f * x; }

// ---------------- x -> fp16 (one-time) -----------------------------------------
__global__ void k_cvt(const float* __restrict__ x, __half* __restrict__ xh, int total)
{
    int i = (blockIdx.x * blockDim.x + threadIdx.x) * 8;
    if (i < total) {
        float4 a = *(const float4*)&x[i];
        float4 b = *(const float4*)&x[i + 4];
        __half2* p = (__half2*)&xh[i];
        p[0] = __floats2half2_rn(a.x, a.y);
        p[1] = __floats2half2_rn(a.z, a.w);
        p[2] = __floats2half2_rn(b.x, b.y);
        p[3] = __floats2half2_rn(b.z, b.w);
    }
}

// ---------------- CSR build ----------------------------------------------------
__global__ void k_zero(int n) {
    int i = blockIdx.x * blockDim.x + threadIdx.x;
    if (i < n) { g_deg[i] = 0; g_cur[i] = 0; }
}

__global__ void k_deg(const int* __restrict__ ei, int E, int n) {
    int i = blockIdx.x * blockDim.x + threadIdx.x;
    int tot = E + n;
    if (i < tot) {
        int dst = (i < E) ? ei[E + i] : (i - E);
        atomicAdd(&g_deg[dst], 1);
    }
}

__global__ __launch_bounds__(1024) void k_part(int n) {
    __shared__ int s[1024];
    int i = blockIdx.x * 1024 + threadIdx.x;
    s[threadIdx.x] = (i < n) ? g_deg[i] : 0;
    __syncthreads();
    for (int off = 512; off > 0; off >>= 1) {
        if (threadIdx.x < off) s[threadIdx.x] += s[threadIdx.x + off];
        __syncthreads();
    }
    if (threadIdx.x == 0) g_part[blockIdx.x] = s[0];
}

__global__ void k_scanp(int nb) {
    __shared__ int s[64];
    int tid = threadIdx.x;
    s[tid] = (tid < nb) ? g_part[tid] : 0;
    __syncthreads();
    for (int off = 1; off < 64; off <<= 1) {
        int t = (tid >= off) ? s[tid - off] : 0;
        __syncthreads();
        s[tid] += t;
        __syncthreads();
    }
    if (tid < nb) g_ppre[tid] = (tid == 0) ? 0 : s[tid - 1];
}

__global__ __launch_bounds__(1024) void k_offsets(int n) {
    __shared__ int s[1024];
    int b = blockIdx.x;
    int i = b * 1024 + threadIdx.x;
    int v = (i < n) ? g_deg[i] : 0;
    s[threadIdx.x] = v;
    __syncthreads();
    for (int off = 1; off < 1024; off <<= 1) {
        int t = (threadIdx.x >= off) ? s[threadIdx.x - off] : 0;
        __syncthreads();
        s[threadIdx.x] += t;
        __syncthreads();
    }
    if (i < n) g_off[i + 1] = g_ppre[b] + s[threadIdx.x];
    if (b == 0 && threadIdx.x == 0) g_off[0] = 0;
}

__global__ void k_scatter(const int* __restrict__ ei, int E, int n) {
    int i = blockIdx.x * blockDim.x + threadIdx.x;
    int tot = E + n;
    if (i < tot) {
        int src, dst;
        if (i < E) { src = ei[i]; dst = ei[E + i]; }
        else       { src = i - E; dst = src; }
        int pos = g_off[dst] + atomicAdd(&g_cur[dst], 1);
        g_srcs[pos] = src;
    }
}

// ---------------- GEMM: 128x64 tile, fp16 A + fp16 HMMA, fused alpha -----------
__global__ __launch_bounds__(256) void k_gemm_tc(
    const __half* __restrict__ A, const float* __restrict__ B, __half* __restrict__ C,
    const float* __restrict__ aS, const float* __restrict__ aD,
    float* __restrict__ gas, float* __restrict__ gad,
    int M, int N, int K)
{
    __shared__ float smem[128 * 68];                 // 34816 B (epilogue Cs)
    __half* Ash = (__half*)smem;                     // [128][40] halfs = 10240 B
    __half* Bsh = (__half*)(smem + 128 * 40 / 2);    // [32][72]  halfs = 4608 B
    float (*Cs)[68] = (float(*)[68])smem;            // epilogue alias

    int tid = threadIdx.x;
    int warp = tid >> 5;
    int row0 = blockIdx.y * 128, col0 = blockIdx.x * 64;
    int wr = (warp & 3) * 32;
    int wc = (warp >> 2) * 32;

    wmma::fragment<wmma::accumulator, 16, 16, 16, float> c[2][2];
#pragma unroll
    for (int i = 0; i < 2; i++)
#pragma unroll
        for (int j = 0; j < 2; j++)
            wmma::fill_fragment(c[i][j], 0.f);

    for (int k0 = 0; k0 < K; k0 += 32) {
        // stage A 128x32 halfs: pure 16B copies
#pragma unroll
        for (int r = 0; r < 2; r++) {
            int idx = tid + r * 256;          // 512 slots
            int m = idx >> 2;                 // 0..127
            int kk = (idx & 3) * 8;           // 0,8,16,24
            uint4 v = make_uint4(0u, 0u, 0u, 0u);
            if (row0 + m < M) v = *(const uint4*)&A[(size_t)(row0 + m) * K + k0 + kk];
            *(uint4*)(Ash + m * 40 + kk) = v;
        }
        // stage B 32x64 fp32 -> fp16
#pragma unroll
        for (int r = 0; r < 2; r++) {
            int idx = tid + r * 256;
            int kk = idx >> 4;
            int nn = (idx & 15) * 4;
            float4 v = *(const float4*)&B[(size_t)(k0 + kk) * N + col0 + nn];
            __half* p = Bsh + kk * 72 + nn;
            *(__half2*)(p + 0) = __floats2half2_rn(v.x, v.y);
            *(__half2*)(p + 2) = __floats2half2_rn(v.z, v.w);
        }
        __syncthreads();
#pragma unroll
        for (int kk = 0; kk < 32; kk += 16) {
            wmma::fragment<wmma::matrix_a, 16, 16, 16, __half, wmma::row_major> a0, a1;
            wmma::fragment<wmma::matrix_b, 16, 16, 16, __half, wmma::row_major> b0, b1;
            wmma::load_matrix_sync(a0, Ash + wr * 40 + kk, 40);
            wmma::load_matrix_sync(a1, Ash + (wr + 16) * 40 + kk, 40);
            wmma::load_matrix_sync(b0, Bsh + kk * 72 + wc, 72);
            wmma::load_matrix_sync(b1, Bsh + kk * 72 + wc + 16, 72);
            wmma::mma_sync(c[0][0], a0, b0, c[0][0]);
            wmma::mma_sync(c[0][1], a0, b1, c[0][1]);
            wmma::mma_sync(c[1][0], a1, b0, c[1][0]);
            wmma::mma_sync(c[1][1], a1, b1, c[1][1]);
        }
        __syncthreads();
    }

    // stage C tile in fp32 smem (aliases staging, safe after sync)
#pragma unroll
    for (int i = 0; i < 2; i++)
#pragma unroll
        for (int j = 0; j < 2; j++)
            wmma::store_matrix_sync(&Cs[wr + i * 16][wc + j * 16], c[i][j], 68, wmma::mem_row_major);
    __syncthreads();

    // write C as fp16 (gather operand only)
    for (int idx = tid; idx < 128 * 32; idx += 256) {
        int m = idx >> 5, nn = (idx & 31) * 2;
        if (row0 + m < M) {
            __half2 hv = __floats2half2_rn(Cs[m][nn], Cs[m][nn + 1]);
            *(__half2*)&C[(size_t)(row0 + m) * N + col0 + nn] = hv;
        }
    }

    // fused alpha: 2 threads per row, 32 cols each (fp32)
    {
        int r = tid >> 1;
        int half = tid & 1;
        float ps = 0.f, pd = 0.f;
#pragma unroll
        for (int cc = 0; cc < 32; cc++) {
            float v = Cs[r][half * 32 + cc];
            ps = fmaf(v, aS[col0 + half * 32 + cc], ps);
            pd = fmaf(v, aD[col0 + half * 32 + cc], pd);
        }
        ps += __shfl_down_sync(0xffffffffu, ps, 1);
        pd += __shfl_down_sync(0xffffffffu, pd, 1);
        if (half == 0 && row0 + r < M) {
            int nh = N >> 6;
            int head = col0 >> 6;
            gas[(row0 + r) * nh + head] = ps;
            gad[(row0 + r) * nh + head] = pd;
        }
    }
}

// ---------------- per-edge weight precompute (warp per node) -------------------
__global__ __launch_bounds__(256) void k_wprep4(
    const float* __restrict__ as, const float* __restrict__ ad, int n)
{
    int warp = threadIdx.x >> 5, lane = threadIdx.x & 31;
    int node = blockIdx.x * 8 + warp;
    if (node >= n) return;
    int beg = g_off[node];
    int deg = g_off[node + 1] - beg;
    float4 adv = *(const float4*)(ad + node * 4);

    float m0 = -1e30f, m1 = -1e30f, m2 = -1e30f, m3 = -1e30f;
    for (int i = lane; i < deg; i += 32) {
        int s = g_srcs[beg + i];
        float4 av = *(const float4*)(as + s * 4);
        m0 = fmaxf(m0, lrelu(av.x + adv.x));
        m1 = fmaxf(m1, lrelu(av.y + adv.y));
        m2 = fmaxf(m2, lrelu(av.z + adv.z));
        m3 = fmaxf(m3, lrelu(av.w + adv.w));
    }
#pragma unroll
    for (int o = 16; o > 0; o >>= 1) {
        m0 = fmaxf(m0, __shfl_xor_sync(0xffffffffu, m0, o));
        m1 = fmaxf(m1, __shfl_xor_sync(0xffffffffu, m1, o));
        m2 = fmaxf(m2, __shfl_xor_sync(0xffffffffu, m2, o));
        m3 = fmaxf(m3, __shfl_xor_sync(0xffffffffu, m3, o));
    }
    float d0 = 0, d1 = 0, d2 = 0, d3 = 0;
    for (int i = lane; i < deg; i += 32) {
        int s = g_srcs[beg + i];
        float4 av = *(const float4*)(as + s * 4);
        float w0 = __expf(lrelu(av.x + adv.x) - m0);
        float w1 = __expf(lrelu(av.y + adv.y) - m1);
        float w2 = __expf(lrelu(av.z + adv.z) - m2);
        float w3 = __expf(lrelu(av.w + adv.w) - m3);
        *(float4*)(g_w + (size_t)(beg + i) * 4) = make_float4(w0, w1, w2, w3);
        d0 += w0; d1 += w1; d2 += w2; d3 += w3;
    }
#pragma unroll
    for (int o = 16; o > 0; o >>= 1) {
        d0 += __shfl_xor_sync(0xffffffffu, d0, o);
        d1 += __shfl_xor_sync(0xffffffffu, d1, o);
        d2 += __shfl_xor_sync(0xffffffffu, d2, o);
        d3 += __shfl_xor_sync(0xffffffffu, d3, o);
    }
    float r0 = 1.f / (d0 + 1e-16f);
    float r1 = 1.f / (d1 + 1e-16f);
    float r2 = 1.f / (d2 + 1e-16f);
    float r3 = 1.f / (d3 + 1e-16f);
    for (int i = lane; i < deg; i += 32) {
        float4 w = *(const float4*)(g_w + (size_t)(beg + i) * 4);
        w.x *= r0; w.y *= r1; w.z *= r2; w.w *= r3;
        *(float4*)(g_w + (size_t)(beg + i) * 4) = w;
    }
}

__global__ __launch_bounds__(256) void k_wprep1(
    const float* __restrict__ as, const float* __restrict__ ad, int n)
{
    int warp = threadIdx.x >> 5, lane = threadIdx.x & 31;
    int node = blockIdx.x * 8 + warp;
    if (node >= n) return;
    int beg = g_off[node];
    int deg = g_off[node + 1] - beg;
    float adv = ad[node];

    float m = -1e30f;
    for (int i = lane; i < deg; i += 32)
        m = fmaxf(m, lrelu(as[g_srcs[beg + i]] + adv));
#pragma unroll
    for (int o = 16; o > 0; o >>= 1)
        m = fmaxf(m, __shfl_xor_sync(0xffffffffu, m, o));
    float d = 0.f;
    for (int i = lane; i < deg; i += 32) {
        float w = __expf(lrelu(as[g_srcs[beg + i]] + adv) - m);
        g_w[beg + i] = w;
        d += w;
    }
#pragma unroll
    for (int o = 16; o > 0; o >>= 1)
        d += __shfl_xor_sync(0xffffffffu, d, o);
    float r = 1.f / (d + 1e-16f);
    for (int i = lane; i < deg; i += 32)
        g_w[beg + i] *= r;
}

// ---------------- GAT aggregation, H=4: fp16 16B gathers, fp16 out -------------
// 8 edge-subgroups x 32 lanes; each lane owns 8 features (16B); smem reduce.
__global__ __launch_bounds__(256) void k_agg4(
    const __half* __restrict__ h, const float* __restrict__ bias,
    __half* __restrict__ out, int elu)
{
    __shared__ float red[256][9];     // stride 9 to avoid bank conflicts (9216 B)
    int n = blockIdx.x, tid = threadIdx.x;
    int sub = tid >> 5;               // edge subgroup 0..7
    int lane = tid & 31;              // feature oct: features 8*lane..8*lane+7
    int head = lane >> 3;
    int beg = g_off[n];
    int deg = g_off[n + 1] - beg;

    float acc[8] = {0, 0, 0, 0, 0, 0, 0, 0};
    int i = sub;
    for (; i + 8 < deg; i += 16) {    // 2-deep unroll (edges i, i+8)
        int s0 = g_srcs[beg + i];
        int s1 = g_srcs[beg + i + 8];
        float w0 = g_w[(size_t)(beg + i) * 4 + head];
        float w1 = g_w[(size_t)(beg + i + 8) * 4 + head];
        uint4 v0 = *(const uint4*)&h[(size_t)s0 * 256 + lane * 8];
        uint4 v1 = *(const uint4*)&h[(size_t)s1 * 256 + lane * 8];
        __half2* p0 = (__half2*)&v0;
        __half2* p1 = (__half2*)&v1;
#pragma unroll
        for (int j = 0; j < 4; j++) {
            float2 f0 = __half22float2(p0[j]);
            float2 f1 = __half22float2(p1[j]);
            acc[2 * j + 0] = fmaf(f0.x, w0, acc[2 * j + 0]);
            acc[2 * j + 1] = fmaf(f0.y, w0, acc[2 * j + 1]);
            acc[2 * j + 0] = fmaf(f1.x, w1, acc[2 * j + 0]);
            acc[2 * j + 1] = fmaf(f1.y, w1, acc[2 * j + 1]);
        }
    }
    for (; i < deg; i += 8) {
        int s = g_srcs[beg + i];
        float w = g_w[(size_t)(beg + i) * 4 + head];
        uint4 v = *(const uint4*)&h[(size_t)s * 256 + lane * 8];
        __half2* p = (__half2*)&v;
#pragma unroll
        for (int j = 0; j < 4; j++) {
            float2 f = __half22float2(p[j]);
            acc[2 * j + 0] = fmaf(f.x, w, acc[2 * j + 0]);
            acc[2 * j + 1] = fmaf(f.y, w, acc[2 * j + 1]);
        }
    }

#pragma unroll
    for (int j = 0; j < 8; j++) red[tid][j] = acc[j];
    __syncthreads();
    if (sub == 0) {
#pragma unroll
        for (int s = 1; s < 8; s++)
#pragma unroll
            for (int j = 0; j < 8; j++)
                acc[j] += red[lane + 32 * s][j];
        __half2 hv[4];
#pragma unroll
        for (int j = 0; j < 4; j++) {
            float v0 = acc[2 * j + 0] + bias[lane * 8 + 2 * j + 0];
            float v1 = acc[2 * j + 1] + bias[lane * 8 + 2 * j + 1];
            if (elu) {
                v0 = v0 > 0.f ? v0 : expm1f(v0);
                v1 = v1 > 0.f ? v1 : expm1f(v1);
            }
            hv[j] = __floats2half2_rn(v0, v1);
        }
        *(uint4*)&out[(size_t)n * 256 + lane * 8] = *(uint4*)hv;
    }
}

// ---------------- GAT aggregation, H=1, F=64: fp16 gather, fp32 out ------------
__global__ __launch_bounds__(64) void k_agg1(
    const __half* __restrict__ h, const float* __restrict__ bias,
    float* __restrict__ out)
{
    int n = blockIdx.x, f = threadIdx.x;
    int beg = g_off[n];
    int deg = g_off[n + 1] - beg;

    float acc = 0.f;
    int i = 0;
    for (; i + 4 <= deg; i += 4) {
        int s0 = g_srcs[beg + i + 0];
        int s1 = g_srcs[beg + i + 1];
        int s2 = g_srcs[beg + i + 2];
        int s3 = g_srcs[beg + i + 3];
        float w0 = g_w[beg + i + 0];
        float w1 = g_w[beg + i + 1];
        float w2 = g_w[beg + i + 2];
        float w3 = g_w[beg + i + 3];
        acc = fmaf(__half2float(h[(size_t)s0 * 64 + f]), w0, acc);
        acc = fmaf(__half2float(h[(size_t)s1 * 64 + f]), w1, acc);
        acc = fmaf(__half2float(h[(size_t)s2 * 64 + f]), w2, acc);
        acc = fmaf(__half2float(h[(size_t)s3 * 64 + f]), w3, acc);
    }
    for (; i < deg; i++)
        acc = fmaf(__half2float(h[(size_t)g_srcs[beg + i] * 64 + f]), g_w[beg + i], acc);
    out[(size_t)n * 64 + f] = acc + bias[f];
}

// ---------------- mean pool over sorted batch ids -----------------------------
__global__ void k_pool(const float* __restrict__ node, const int* __restrict__ batch,
                       float* __restrict__ gout, int n)
{
    int g = blockIdx.x;
    int lo = 0, hi = n;
    while (lo < hi) { int mid = (lo + hi) >> 1; if (batch[mid] < g) lo = mid + 1; else hi = mid; }
    int start = lo;
    lo = start; hi = n;
    while (lo < hi) { int mid = (lo + hi) >> 1; if (batch[mid] < g + 1) lo = mid + 1; else hi = mid; }
    int end = lo;

    int f = threadIdx.x & 63;
    int sub = threadIdx.x >> 6;
    float acc = 0.f;
    for (int i = start + sub; i < end; i += 4)
        acc += node[(size_t)i * 64 + f];
    __shared__ float s[256];
    s[threadIdx.x] = acc;
    __syncthreads();
    if (threadIdx.x < 64) {
        float v = s[threadIdx.x] + s[threadIdx.x + 64] + s[threadIdx.x + 128] + s[threadIdx.x + 192];
        int cnt = end - start;
        gout[g * 64 + threadIdx.x] = v / (float)max(cnt, 1);
    }
}

// ---------------- host side ----------------------------------------------------
extern "C" void kernel_launch(void* const* d_in, const int* in_sizes, int n_in,
                              void* d_out, int out_size)
{
    const float* x    = (const float*)d_in[0];
    const int*   ei   = (const int*)d_in[1];
    const int*   batch= (const int*)d_in[2];
    const float* W1   = (const float*)d_in[3];
    const float* as1  = (const float*)d_in[4];
    const float* ad1  = (const float*)d_in[5];
    const float* b1   = (const float*)d_in[6];
    const float* W2   = (const float*)d_in[7];
    const float* as2  = (const float*)d_in[8];
    const float* ad2  = (const float*)d_in[9];
    const float* b2   = (const float*)d_in[10];
    const float* W3   = (const float*)d_in[11];
    const float* as3  = (const float*)d_in[12];
    const float* ad3  = (const float*)d_in[13];
    const float* b3   = (const float*)d_in[14];

    int n = in_sizes[0] / 256;
    int E = in_sizes[1] / 2;
    float* out = (float*)d_out;
    int G = (out_size - n * 64) / 64;

    float *p_as, *p_ad;
    __half *p_xh, *p_h, *p_h2;
    cudaGetSymbolAddress((void**)&p_xh, g_xh);
    cudaGetSymbolAddress((void**)&p_h,  g_h);
    cudaGetSymbolAddress((void**)&p_h2, g_h2h);
    cudaGetSymbolAddress((void**)&p_as, g_as);
    cudaGetSymbolAddress((void**)&p_ad, g_ad);

    int tot = E + n;
    int nb = (n + 1023) / 1024;
    int nw = (n + 7) / 8;
    int tf = n * 256;

    dim3 gbig(4, (n + 127) / 128);     // 128x64 tiles, N=256
    dim3 gsm(1, (n + 127) / 128);      // 128x64 tile,  N=64

    // Launch index 3 = layer-1 GEMM so ncu (which profiles launch #3) shows it.
    k_cvt<<<(tf / 8 + 255) / 256, 256>>>(x, p_xh, tf);                          // 0
    k_zero<<<(n + 255) / 256, 256>>>(n);                                        // 1
    k_deg<<<(tot + 255) / 256, 256>>>(ei, E, n);                                // 2
    k_gemm_tc<<<gbig, 256>>>(p_xh, W1, p_h2, as1, ad1, p_as, p_ad, n, 256, 256);// 3
    k_part<<<nb, 1024>>>(n);                                                    // 4
    k_scanp<<<1, 64>>>(nb);                                                     // 5
    k_offsets<<<nb, 1024>>>(n);                                                 // 6
    k_scatter<<<(tot + 255) / 256, 256>>>(ei, E, n);                            // 7

    // layer 1 (cont.)
    k_wprep4<<<nw, 256>>>(p_as, p_ad, n);
    k_agg4<<<n, 256>>>(p_h2, b1, p_h, 1);
    // layer 2
    k_gemm_tc<<<gbig, 256>>>(p_h, W2, p_h2, as2, ad2, p_as, p_ad, n, 256, 256);
    k_wprep4<<<nw, 256>>>(p_as, p_ad, n);
    k_agg4<<<n, 256>>>(p_h2, b2, p_h, 1);
    // layer 3
    k_gemm_tc<<<gsm, 256>>>(p_h, W3, p_h2, as3, ad3, p_as, p_ad, n, 64, 256);
    k_wprep1<<<nw, 256>>>(p_as, p_ad, n);
    k_agg1<<<n, 64>>>(p_h2, b3, out);
    // pooling
    k_pool<<<G, 256>>>(out, batch, out + n * 64, n);
}